// round 16
// baseline (speedup 1.0000x reference)
#include <cuda_runtime.h>
#include <cstdint>

#define NCOL  49152                    // OC*IC*KW
#define W2D_ELEMS 37748736ULL          // 2048*2048*3*3
#define GRID  296                      // 2 CTAs/SM persistent (== exact residency)
#define NTILES 1024

// ---- scratch ----
__device__ float g_partf[64 * 256];                 // per-block partial pde features
__device__ __align__(16) float g_hidP[256 * 256];   // hidden, mma-A-fragment packed, tf32-rounded
__device__ volatile unsigned g_c1;                  // phase-A arrivals (blocks 0..63)
__device__ volatile unsigned g_c2;                  // phase-B arrivals (blocks 0..255)
__device__ unsigned g_fin;                          // completion counter (self-reset)

// ---- helpers ----
__device__ __forceinline__ void cp16(void* dst_smem, const void* src) {
    unsigned u = (unsigned)__cvta_generic_to_shared(dst_smem);
    asm volatile("cp.async.cg.shared.global [%0],[%1],16;" :: "r"(u), "l"(src));
}
#define CP_COMMIT() asm volatile("cp.async.commit_group;")
#define CP_WAIT1()  asm volatile("cp.async.wait_group 1;")

__device__ __forceinline__ uint32_t to_tf32(float f) {
    uint32_t u; asm("cvt.rna.tf32.f32 %0,%1;" : "=r"(u) : "f"(f)); return u;
}
#define MMA_TF32(d, a0, a1, a2, a3, b0, b1)                                   \
    asm volatile("mma.sync.aligned.m16n8k8.row.col.f32.tf32.tf32.f32 "        \
        "{%0,%1,%2,%3},{%4,%5,%6,%7},{%8,%9},{%0,%1,%2,%3};"                  \
        : "+f"((d)[0]), "+f"((d)[1]), "+f"((d)[2]), "+f"((d)[3])              \
        : "r"(a0), "r"(a1), "r"(a2), "r"(a3), "r"(b0), "r"(b1))

// ================= single persistent kernel =================
#define BSTRIDE 104                   // 96 + 8 pad (conflict-free b LDS)
#define BSTAGE  (32 * BSTRIDE)        // 3328 floats
#define STG_STRIDE 56                 // staging row stride (STS conflict-free)
#define OSTG_OFF (3 * BSTAGE + 8 * 8 * STG_STRIDE)
#define USM_OFF  (OSTG_OFF + 8 * 1152)
#define SMEM_BYTES ((USM_OFF + 8 * 384) * 4)

__global__ __launch_bounds__(256, 2) void k_tc(const float* __restrict__ W2,
                                               const float* __restrict__ b2,
                                               const float* __restrict__ unet,
                                               float* __restrict__ out,
                                               const float* __restrict__ pde,
                                               const float* __restrict__ U1,
                                               const float* __restrict__ b1,
                                               const float* __restrict__ Z,
                                               const float* __restrict__ W1,
                                               const float* __restrict__ z_bias,
                                               const float* __restrict__ u_bias) {
    extern __shared__ float smem[];
    __shared__ float p_sm[256];
    __shared__ float p_red[64];
    float* Bsm = smem;
    int tid  = threadIdx.x;
    int lane = tid & 31, wid = tid >> 5;
    int wm = wid & 3, wn = wid >> 2;
    float* stgW = smem + 3 * BSTAGE + wid * (8 * STG_STRIDE);
    float* ostW = smem + OSTG_OFF + wid * 1152;   // per-warp w out-stage (8 rows x 144)
    float* uSmW = smem + USM_OFF + wid * 384;     // per-warp unet stage (8 rows x 48)
    int row8 = lane >> 2, seg = lane & 3;        // epilogue roles
    int g = row8, q = seg;                        // fragment roles

    int t0 = blockIdx.x;
    int rt = t0 & 1;                              // constant per CTA (GRID even)
    const float* aB0 = g_hidP + (size_t)(rt * 8 + wm * 2) * 4096;
    const float* aB1 = aB0 + 4096;

    auto pf = [&](int nt, int c, int st) {
        const float* src = W2 + (size_t)(c * 32) * NCOL + (size_t)(nt >> 1) * 96;
        float* dst = Bsm + st * BSTAGE;
        #pragma unroll
        for (int i = 0; i < 3; ++i) {
            int idx = i * 256 + tid;            // 0..767 float4s: 32 rows x 24
            int row = idx / 24, c4 = idx - row * 24;
            cp16(dst + row * BSTRIDE + c4 * 4, src + (size_t)row * NCOL + c4 * 4);
        }
    };

    // ---- kick off first two B fills immediately (independent of prolog) ----
    pf(t0, 0, 0); CP_COMMIT();
    pf(t0, 1, 1); CP_COMMIT();
    int stw = 2, strd = 0;

    // ================= fused prolog =================
    // Phase A: blocks 0..63 -> partial pde feature; blocks 64..71 -> bb tail
    if (t0 < 64) {
        int d = tid & 63, sl = tid >> 6;
        float s = 0.f;
        #pragma unroll
        for (int it = 0; it < 4; ++it) s += pde[(t0 * 16 + sl + it * 4) * 64 + d];
        p_sm[tid] = s;
        __syncthreads();
        if (tid < 64)
            p_red[tid] = p_sm[tid] + p_sm[tid + 64] + p_sm[tid + 128] + p_sm[tid + 192];
        __syncthreads();
        float acc = 0.f;
        #pragma unroll 8
        for (int d2 = 0; d2 < 64; ++d2) acc += p_red[d2] * U1[d2 * 256 + tid];
        g_partf[t0 * 256 + tid] = acc;
        __threadfence();
        __syncthreads();
        if (tid == 0) atomicAdd((unsigned*)&g_c1, 1u);
    } else if (t0 < 72) {
        int o = (t0 - 64) * 256 + tid;
        out[W2D_ELEMS + o] = z_bias[o] + u_bias[o];
    }

    // Phase B: blocks 0..255 compute one hidden row each
    if (t0 < 256) {
        int r = t0;
        if (tid < 64) p_red[tid] = Z[r * 64 + tid];     // reuse p_red as z row
        if (tid == 0) { while (g_c1 < 64) __nanosleep(64); }
        __syncthreads();
        __threadfence();
        float acc = b1[tid];
        float fs = 0.f;
        #pragma unroll 8
        for (int b = 0; b < 64; ++b) fs += g_partf[b * 256 + tid];
        acc += fs * (1.0f / 1024.0f);
        #pragma unroll 8
        for (int d = 0; d < 64; ++d) acc += p_red[d] * W1[d * 256 + tid];
        uint32_t tf = to_tf32(tanhf(acc));
        int rrt = r >> 7, m = r & 127, mt = m >> 4, mr = m & 15;
        int gg = mr & 7, jb0 = mr >> 3;
        int qq = tid & 3, jb1 = (tid >> 2) & 1, ks = tid >> 3;
        int ln = gg * 4 + qq, j = jb0 + 2 * jb1;
        g_hidP[(((rrt * 8 + mt) * 32 + ks) * 32 + ln) * 4 + j] = __uint_as_float(tf);
        __threadfence();
        __syncthreads();
        if (tid == 0) atomicAdd((unsigned*)&g_c2, 1u);
    }

    // Phase C: everyone waits for hidden to be complete
    if (tid == 0) { while (g_c2 < 256) __nanosleep(64); }
    __syncthreads();
    __threadfence();

    // ================= tile loop (byte-identical to 86.5us winner) =================
    #pragma unroll 1
    for (int tile = t0; tile < NTILES; tile += GRID) {
        int ct = tile >> 1;
        float acc[2][6][4];
        #pragma unroll
        for (int tt = 0; tt < 2; ++tt)
            #pragma unroll
            for (int u = 0; u < 6; ++u)
                #pragma unroll
                for (int e = 0; e < 4; ++e) acc[tt][u][e] = 0.f;

        #pragma unroll 1
        for (int c = 0; c < 8; ++c) {
            CP_WAIT1();
            __syncthreads();
            int nt = tile, nc = c + 2;
            if (nc >= 8) { nt += GRID; nc -= 8; }
            if (nt < NTILES) pf(nt, nc, stw);
            CP_COMMIT();
            stw = (stw == 2) ? 0 : stw + 1;

            const float* buf = Bsm + strd * BSTAGE;
            #pragma unroll
            for (int ks = 0; ks < 4; ++ks) {
                int kk = c * 4 + ks;
                float4 fa0 = *(const float4*)(aB0 + (size_t)(kk * 32 + lane) * 4);
                float4 fa1 = *(const float4*)(aB1 + (size_t)(kk * 32 + lane) * 4);
                const float* bk0 = buf + (ks * 8 + q) * BSTRIDE + wn * 48 + g;
                const float* bk1 = bk0 + 4 * BSTRIDE;
                uint32_t br0[6], br1[6];
                #pragma unroll
                for (int u = 0; u < 6; ++u) {
                    br0[u] = __float_as_uint(bk0[u * 8]);   // raw fp32 -> HW tf32 trunc
                    br1[u] = __float_as_uint(bk1[u * 8]);
                }
                uint32_t a00 = __float_as_uint(fa0.x), a01 = __float_as_uint(fa0.y),
                         a02 = __float_as_uint(fa0.z), a03 = __float_as_uint(fa0.w);
                uint32_t a10 = __float_as_uint(fa1.x), a11 = __float_as_uint(fa1.y),
                         a12 = __float_as_uint(fa1.z), a13 = __float_as_uint(fa1.w);
                #pragma unroll
                for (int u = 0; u < 6; ++u) {
                    MMA_TF32(acc[0][u], a00, a01, a02, a03, br0[u], br1[u]);
                    MMA_TF32(acc[1][u], a10, a11, a12, a13, br0[u], br1[u]);
                }
            }
            strd = (strd == 2) ? 0 : strd + 1;
        }

        // ---------- epilogue ----------
        float b2r[12];
        {
            const float* bp = b2 + ct * 96 + wn * 48 + 2 * q;
            #pragma unroll
            for (int u = 0; u < 6; ++u) {
                float2 tv = *(const float2*)(bp + u * 8);
                b2r[2 * u] = tv.x; b2r[2 * u + 1] = tv.y;
            }
        }
        auto uload = [&](int rg, float4* v) {
            int rbase = rt * 128 + wm * 32 + rg * 8;
            int o = ((rbase >> 4) << 7) + (ct >> 2);
            #pragma unroll
            for (int it = 0; it < 3; ++it) {
                int idx = it * 32 + lane;            // 0..95
                int row = idx / 12, cc = idx - row * 12;
                int r = rbase + row;
                int i0 = ((r & 15) << 7) + ((ct & 3) << 5) + wn * 16;
                v[it] = __ldcs((const float4*)(unet + ((size_t)o * 2048 + i0) * 3) + cc);
            }
        };
        float4 uvr[3];
        uload(0, uvr);

        #pragma unroll
        for (int rg = 0; rg < 4; ++rg) {
            int tt = rg >> 1, hi = rg & 1;
            #pragma unroll
            for (int it = 0; it < 3; ++it)
                *(float4*)&uSmW[(it * 32 + lane) * 4] = uvr[it];
            #pragma unroll
            for (int u = 0; u < 6; ++u) {
                float2 e;
                e.x = acc[tt][u][hi * 2 + 0] + b2r[2 * u];
                e.y = acc[tt][u][hi * 2 + 1] + b2r[2 * u + 1];
                *(float2*)&stgW[g * STG_STRIDE + u * 8 + 2 * q] = e;
            }
            __syncwarp();
            if (rg < 3) uload(rg + 1, uvr);
            float4 s0 = *(const float4*)&stgW[row8 * STG_STRIDE + seg * 12 + 0];
            float4 s1 = *(const float4*)&stgW[row8 * STG_STRIDE + seg * 12 + 4];
            float4 s2 = *(const float4*)&stgW[row8 * STG_STRIDE + seg * 12 + 8];
            float4 u0 = *(const float4*)&uSmW[row8 * 48 + seg * 12 + 0];
            float4 u1 = *(const float4*)&uSmW[row8 * 48 + seg * 12 + 4];
            float4 u2 = *(const float4*)&uSmW[row8 * 48 + seg * 12 + 8];
            float sv[12] = { s0.x, s0.y, s0.z, s0.w, s1.x, s1.y, s1.z, s1.w,
                             s2.x, s2.y, s2.z, s2.w };
            float uv[12] = { u0.x, u0.y, u0.z, u0.w, u1.x, u1.y, u1.z, u1.w,
                             u2.x, u2.y, u2.z, u2.w };
            #pragma unroll
            for (int jj = 0; jj < 9; ++jj) {
                float v[4];
                #pragma unroll
                for (int e = 0; e < 4; ++e) {
                    int j = jj * 4 + e;
                    int p = j / 9, rem = j - p * 9;
                    int kq = rem / 3, l = rem - kq * 3;
                    v[e] = sv[p * 3 + kq] * uv[p * 3 + l];
                }
                *(float4*)&ostW[row8 * 144 + seg * 36 + jj * 4] =
                    make_float4(v[0], v[1], v[2], v[3]);
            }
            __syncwarp();
            #pragma unroll
            for (int row = 0; row < 8; ++row) {
                int r = rt * 128 + wm * 32 + rg * 8 + row;
                int o  = ((r >> 4) << 7) + (ct >> 2);
                int i0 = ((r & 15) << 7) + ((ct & 3) << 5) + wn * 16;
                float4* gb = (float4*)(out + ((size_t)o * 2048 + i0) * 9);
                float4 tA = *(const float4*)&ostW[row * 144 + lane * 4];
                __stcs(gb + lane, tA);
                if (lane < 4) {
                    float4 tB = *(const float4*)&ostW[row * 144 + 128 + lane * 4];
                    __stcs(gb + 32 + lane, tB);
                }
            }
            __syncwarp();
        }
    }

    // ---- self-reset for graph replay (all 296 CTAs resident -> safe) ----
    __syncthreads();
    if (tid == 0) {
        __threadfence();
        unsigned v = atomicAdd(&g_fin, 1u);
        if (v == GRID - 1) {
            g_fin = 0;
            *(unsigned*)&g_c1 = 0;
            *(unsigned*)&g_c2 = 0;
            __threadfence();
        }
    }
}

extern "C" void kernel_launch(void* const* d_in, const int* in_sizes, int n_in,
                              void* d_out, int out_size) {
    const float* Z      = (const float*)d_in[0];
    const float* z_bias = (const float*)d_in[1];
    const float* unet_w = (const float*)d_in[2];
    const float* unet_b = (const float*)d_in[3];
    const float* pde    = (const float*)d_in[4];
    const float* W1     = (const float*)d_in[5];
    const float* U1     = (const float*)d_in[6];
    const float* b1     = (const float*)d_in[7];
    const float* W2     = (const float*)d_in[8];
    const float* b2     = (const float*)d_in[9];
    float* out = (float*)d_out;

    cudaFuncSetAttribute(k_tc, cudaFuncAttributeMaxDynamicSharedMemorySize, SMEM_BYTES);

    k_tc<<<GRID, 256, SMEM_BYTES>>>(W2, b2, unet_w, out,
                                    pde, U1, b1, Z, W1, z_bias, unet_b);
}

// round 17
// speedup vs baseline: 1.0084x; 1.0084x over previous
#include <cuda_runtime.h>
#include <cstdint>

#define NCOL  49152                    // OC*IC*KW
#define W2D_ELEMS 37748736ULL          // 2048*2048*3*3
#define GRID  296                      // 2 CTAs/SM persistent (== exact residency)
#define NTILES 1024

// ---- scratch ----
__device__ float g_partf[64 * 256];                 // per-block partial pde features
__device__ __align__(16) float g_hidP[256 * 256];   // hidden, mma-A-fragment packed, tf32-rounded
__device__ volatile unsigned g_c1;                  // phase-A arrivals (blocks 0..63)
__device__ volatile unsigned g_c2;                  // phase-B arrivals (blocks 0..255)
__device__ unsigned g_fin;                          // completion counter (self-reset)

// ---- helpers ----
__device__ __forceinline__ void cp16(void* dst_smem, const void* src) {
    unsigned u = (unsigned)__cvta_generic_to_shared(dst_smem);
    asm volatile("cp.async.cg.shared.global [%0],[%1],16;" :: "r"(u), "l"(src));
}
#define CP_COMMIT() asm volatile("cp.async.commit_group;")
#define CP_WAIT1()  asm volatile("cp.async.wait_group 1;")

__device__ __forceinline__ uint32_t to_tf32(float f) {
    uint32_t u; asm("cvt.rna.tf32.f32 %0,%1;" : "=r"(u) : "f"(f)); return u;
}
#define MMA_TF32(d, a0, a1, a2, a3, b0, b1)                                   \
    asm volatile("mma.sync.aligned.m16n8k8.row.col.f32.tf32.tf32.f32 "        \
        "{%0,%1,%2,%3},{%4,%5,%6,%7},{%8,%9},{%0,%1,%2,%3};"                  \
        : "+f"((d)[0]), "+f"((d)[1]), "+f"((d)[2]), "+f"((d)[3])              \
        : "r"(a0), "r"(a1), "r"(a2), "r"(a3), "r"(b0), "r"(b1))

// ================= single persistent kernel =================
#define BSTRIDE 104                   // 96 + 8 pad (conflict-free b LDS)
#define BSTAGE  (32 * BSTRIDE)        // 3328 floats
#define STG_STRIDE 56                 // staging row stride (STS conflict-free)
#define OSTG_OFF (3 * BSTAGE + 8 * 8 * STG_STRIDE)
#define USM_OFF  (OSTG_OFF + 8 * 1152)
#define SMEM_BYTES ((USM_OFF + 8 * 384) * 4)

__global__ __launch_bounds__(256, 2) void k_tc(const float* __restrict__ W2,
                                               const float* __restrict__ b2,
                                               const float* __restrict__ unet,
                                               float* __restrict__ out,
                                               const float* __restrict__ pde,
                                               const float* __restrict__ U1,
                                               const float* __restrict__ b1,
                                               const float* __restrict__ Z,
                                               const float* __restrict__ W1,
                                               const float* __restrict__ z_bias,
                                               const float* __restrict__ u_bias) {
    extern __shared__ float smem[];
    __shared__ float p_sm[256];
    __shared__ float p_red[64];
    float* Bsm = smem;
    int tid  = threadIdx.x;
    int lane = tid & 31, wid = tid >> 5;
    int wm = wid & 3, wn = wid >> 2;
    float* stgW = smem + 3 * BSTAGE + wid * (8 * STG_STRIDE);
    float* ostW = smem + OSTG_OFF + wid * 1152;   // per-warp w out-stage (8 rows x 144)
    float* uSmW = smem + USM_OFF + wid * 384;     // per-warp unet stage (8 rows x 48)
    int row8 = lane >> 2, seg = lane & 3;        // epilogue roles
    int g = row8, q = seg;                        // fragment roles

    int t0 = blockIdx.x;
    int rt = t0 & 1;                              // constant per CTA (GRID even)
    const float* aB0 = g_hidP + (size_t)(rt * 8 + wm * 2) * 4096;
    const float* aB1 = aB0 + 4096;

    auto pf = [&](int nt, int c, int st) {
        const float* src = W2 + (size_t)(c * 32) * NCOL + (size_t)(nt >> 1) * 96;
        float* dst = Bsm + st * BSTAGE;
        #pragma unroll
        for (int i = 0; i < 3; ++i) {
            int idx = i * 256 + tid;            // 0..767 float4s: 32 rows x 24
            int row = idx / 24, c4 = idx - row * 24;
            cp16(dst + row * BSTRIDE + c4 * 4, src + (size_t)row * NCOL + c4 * 4);
        }
    };

    // ================= fused prolog (BEFORE any W2 fill flood) =================
    // Phase A: blocks 0..63 -> partial pde feature; blocks 64..71 -> bb tail
    if (t0 < 64) {
        int d = tid & 63, sl = tid >> 6;
        float s = 0.f;
        #pragma unroll
        for (int it = 0; it < 4; ++it) s += pde[(t0 * 16 + sl + it * 4) * 64 + d];
        p_sm[tid] = s;
        __syncthreads();
        if (tid < 64)
            p_red[tid] = p_sm[tid] + p_sm[tid + 64] + p_sm[tid + 128] + p_sm[tid + 192];
        __syncthreads();
        float acc = 0.f;
        #pragma unroll 8
        for (int d2 = 0; d2 < 64; ++d2) acc += p_red[d2] * U1[d2 * 256 + tid];
        g_partf[t0 * 256 + tid] = acc;
        __threadfence();
        __syncthreads();
        if (tid == 0) atomicAdd((unsigned*)&g_c1, 1u);
    } else if (t0 < 72) {
        int o = (t0 - 64) * 256 + tid;
        out[W2D_ELEMS + o] = z_bias[o] + u_bias[o];
    }

    // Non-prolog CTAs (>=256): start their fills immediately (small flood: 40 CTAs)
    if (t0 >= 256) {
        pf(t0, 0, 0); CP_COMMIT();
        pf(t0, 1, 1); CP_COMMIT();
    }

    // Phase B: blocks 0..255 compute one hidden row each (DRAM still quiet)
    if (t0 < 256) {
        int r = t0;
        __syncthreads();                                // A's p_red reads done
        if (tid < 64) p_red[tid] = Z[r * 64 + tid];     // reuse p_red as z row
        if (tid == 0) { while (g_c1 < 64) __nanosleep(64); }
        __syncthreads();
        __threadfence();
        float acc = b1[tid];
        float fs = 0.f;
        #pragma unroll 8
        for (int b = 0; b < 64; ++b) fs += g_partf[b * 256 + tid];
        acc += fs * (1.0f / 1024.0f);
        #pragma unroll 8
        for (int d = 0; d < 64; ++d) acc += p_red[d] * W1[d * 256 + tid];
        uint32_t tf = to_tf32(tanhf(acc));
        int rrt = r >> 7, m = r & 127, mt = m >> 4, mr = m & 15;
        int gg = mr & 7, jb0 = mr >> 3;
        int qq = tid & 3, jb1 = (tid >> 2) & 1, ks = tid >> 3;
        int ln = gg * 4 + qq, j = jb0 + 2 * jb1;
        g_hidP[(((rrt * 8 + mt) * 32 + ks) * 32 + ln) * 4 + j] = __uint_as_float(tf);
        __threadfence();
        __syncthreads();
        if (tid == 0) atomicAdd((unsigned*)&g_c2, 1u);
        // fills issued only after prolog roles complete
        pf(t0, 0, 0); CP_COMMIT();
        pf(t0, 1, 1); CP_COMMIT();
    }
    int stw = 2, strd = 0;

    // Phase C: everyone waits for hidden to be complete (fills in flight meanwhile)
    if (tid == 0) { while (g_c2 < 256) __nanosleep(64); }
    __syncthreads();
    __threadfence();

    // ================= tile loop (byte-identical to 86.5us winner) =================
    #pragma unroll 1
    for (int tile = t0; tile < NTILES; tile += GRID) {
        int ct = tile >> 1;
        float acc[2][6][4];
        #pragma unroll
        for (int tt = 0; tt < 2; ++tt)
            #pragma unroll
            for (int u = 0; u < 6; ++u)
                #pragma unroll
                for (int e = 0; e < 4; ++e) acc[tt][u][e] = 0.f;

        #pragma unroll 1
        for (int c = 0; c < 8; ++c) {
            CP_WAIT1();
            __syncthreads();
            int nt = tile, nc = c + 2;
            if (nc >= 8) { nt += GRID; nc -= 8; }
            if (nt < NTILES) pf(nt, nc, stw);
            CP_COMMIT();
            stw = (stw == 2) ? 0 : stw + 1;

            const float* buf = Bsm + strd * BSTAGE;
            #pragma unroll
            for (int ks = 0; ks < 4; ++ks) {
                int kk = c * 4 + ks;
                float4 fa0 = *(const float4*)(aB0 + (size_t)(kk * 32 + lane) * 4);
                float4 fa1 = *(const float4*)(aB1 + (size_t)(kk * 32 + lane) * 4);
                const float* bk0 = buf + (ks * 8 + q) * BSTRIDE + wn * 48 + g;
                const float* bk1 = bk0 + 4 * BSTRIDE;
                uint32_t br0[6], br1[6];
                #pragma unroll
                for (int u = 0; u < 6; ++u) {
                    br0[u] = __float_as_uint(bk0[u * 8]);   // raw fp32 -> HW tf32 trunc
                    br1[u] = __float_as_uint(bk1[u * 8]);
                }
                uint32_t a00 = __float_as_uint(fa0.x), a01 = __float_as_uint(fa0.y),
                         a02 = __float_as_uint(fa0.z), a03 = __float_as_uint(fa0.w);
                uint32_t a10 = __float_as_uint(fa1.x), a11 = __float_as_uint(fa1.y),
                         a12 = __float_as_uint(fa1.z), a13 = __float_as_uint(fa1.w);
                #pragma unroll
                for (int u = 0; u < 6; ++u) {
                    MMA_TF32(acc[0][u], a00, a01, a02, a03, br0[u], br1[u]);
                    MMA_TF32(acc[1][u], a10, a11, a12, a13, br0[u], br1[u]);
                }
            }
            strd = (strd == 2) ? 0 : strd + 1;
        }

        // ---------- epilogue ----------
        float b2r[12];
        {
            const float* bp = b2 + ct * 96 + wn * 48 + 2 * q;
            #pragma unroll
            for (int u = 0; u < 6; ++u) {
                float2 tv = *(const float2*)(bp + u * 8);
                b2r[2 * u] = tv.x; b2r[2 * u + 1] = tv.y;
            }
        }
        auto uload = [&](int rg, float4* v) {
            int rbase = rt * 128 + wm * 32 + rg * 8;
            int o = ((rbase >> 4) << 7) + (ct >> 2);
            #pragma unroll
            for (int it = 0; it < 3; ++it) {
                int idx = it * 32 + lane;            // 0..95
                int row = idx / 12, cc = idx - row * 12;
                int r = rbase + row;
                int i0 = ((r & 15) << 7) + ((ct & 3) << 5) + wn * 16;
                v[it] = __ldcs((const float4*)(unet + ((size_t)o * 2048 + i0) * 3) + cc);
            }
        };
        float4 uvr[3];
        uload(0, uvr);

        #pragma unroll
        for (int rg = 0; rg < 4; ++rg) {
            int tt = rg >> 1, hi = rg & 1;
            #pragma unroll
            for (int it = 0; it < 3; ++it)
                *(float4*)&uSmW[(it * 32 + lane) * 4] = uvr[it];
            #pragma unroll
            for (int u = 0; u < 6; ++u) {
                float2 e;
                e.x = acc[tt][u][hi * 2 + 0] + b2r[2 * u];
                e.y = acc[tt][u][hi * 2 + 1] + b2r[2 * u + 1];
                *(float2*)&stgW[g * STG_STRIDE + u * 8 + 2 * q] = e;
            }
            __syncwarp();
            if (rg < 3) uload(rg + 1, uvr);
            float4 s0 = *(const float4*)&stgW[row8 * STG_STRIDE + seg * 12 + 0];
            float4 s1 = *(const float4*)&stgW[row8 * STG_STRIDE + seg * 12 + 4];
            float4 s2 = *(const float4*)&stgW[row8 * STG_STRIDE + seg * 12 + 8];
            float4 u0 = *(const float4*)&uSmW[row8 * 48 + seg * 12 + 0];
            float4 u1 = *(const float4*)&uSmW[row8 * 48 + seg * 12 + 4];
            float4 u2 = *(const float4*)&uSmW[row8 * 48 + seg * 12 + 8];
            float sv[12] = { s0.x, s0.y, s0.z, s0.w, s1.x, s1.y, s1.z, s1.w,
                             s2.x, s2.y, s2.z, s2.w };
            float uv[12] = { u0.x, u0.y, u0.z, u0.w, u1.x, u1.y, u1.z, u1.w,
                             u2.x, u2.y, u2.z, u2.w };
            #pragma unroll
            for (int jj = 0; jj < 9; ++jj) {
                float v[4];
                #pragma unroll
                for (int e = 0; e < 4; ++e) {
                    int j = jj * 4 + e;
                    int p = j / 9, rem = j - p * 9;
                    int kq = rem / 3, l = rem - kq * 3;
                    v[e] = sv[p * 3 + kq] * uv[p * 3 + l];
                }
                *(float4*)&ostW[row8 * 144 + seg * 36 + jj * 4] =
                    make_float4(v[0], v[1], v[2], v[3]);
            }
            __syncwarp();
            #pragma unroll
            for (int row = 0; row < 8; ++row) {
                int r = rt * 128 + wm * 32 + rg * 8 + row;
                int o  = ((r >> 4) << 7) + (ct >> 2);
                int i0 = ((r & 15) << 7) + ((ct & 3) << 5) + wn * 16;
                float4* gb = (float4*)(out + ((size_t)o * 2048 + i0) * 9);
                float4 tA = *(const float4*)&ostW[row * 144 + lane * 4];
                __stcs(gb + lane, tA);
                if (lane < 4) {
                    float4 tB = *(const float4*)&ostW[row * 144 + 128 + lane * 4];
                    __stcs(gb + 32 + lane, tB);
                }
            }
            __syncwarp();
        }
    }

    // ---- self-reset for graph replay (all 296 CTAs resident -> safe) ----
    __syncthreads();
    if (tid == 0) {
        __threadfence();
        unsigned v = atomicAdd(&g_fin, 1u);
        if (v == GRID - 1) {
            g_fin = 0;
            *(unsigned*)&g_c1 = 0;
            *(unsigned*)&g_c2 = 0;
            __threadfence();
        }
    }
}

extern "C" void kernel_launch(void* const* d_in, const int* in_sizes, int n_in,
                              void* d_out, int out_size) {
    const float* Z      = (const float*)d_in[0];
    const float* z_bias = (const float*)d_in[1];
    const float* unet_w = (const float*)d_in[2];
    const float* unet_b = (const float*)d_in[3];
    const float* pde    = (const float*)d_in[4];
    const float* W1     = (const float*)d_in[5];
    const float* U1     = (const float*)d_in[6];
    const float* b1     = (const float*)d_in[7];
    const float* W2     = (const float*)d_in[8];
    const float* b2     = (const float*)d_in[9];
    float* out = (float*)d_out;

    cudaFuncSetAttribute(k_tc, cudaFuncAttributeMaxDynamicSharedMemorySize, SMEM_BYTES);

    k_tc<<<GRID, 256, SMEM_BYTES>>>(W2, b2, unet_w, out,
                                    pde, U1, b1, Z, W1, z_bias, unet_b);
}